// round 8
// baseline (speedup 1.0000x reference)
#include <cuda_runtime.h>
#include <math.h>

#define T_BUCKETS 8192
#define HBLK 1184
#define HTHR 256
#define FIN_THREADS 1024

#define CNT_STEP 2048.0f     // count carrier in P slot
#define OBS_STEP 16384.0f    // obs-count carrier in S slot

// Per-bucket packed accumulator {S + obs_cnt*16384, P + m*2048} (64 KB, L2).
// Zero at module load; scan_kernel re-zeros it each launch.
__device__ float2 g_acc2[T_BUCKETS];

// epilogue intermediates
__device__ double g_R[T_BUCKETS];   // suffix sums of S
__device__ float  g_Sv[T_BUCKETS];
__device__ float  g_Pv[T_BUCKETS];
__device__ int    g_Mv[T_BUCKETS];  // count, sign bit used for obs flag? keep separate
__device__ int    g_Ov[T_BUCKETS];
__device__ double g_loss;           // zero at load; finalize resets

// ---------------------------------------------------------------------------
// Kernel 1: streaming pass — ONE red.global.add.v2.f32 (64-bit) per element.
// All four aggregates (S, P, count, obs) ride in the two f32 lanes via
// fixed-point carriers. High occupancy (8 blocks/SM) to hide REDG issue.
// ---------------------------------------------------------------------------
__device__ __forceinline__ void acc_one(float p, int t, int o) {
    float s = __expf(p) + (o ? OBS_STEP : 0.0f);
    float q = p + CNT_STEP;
    asm volatile("red.global.add.v2.f32 [%0], {%1, %2};"
                 :: "l"(&g_acc2[t]), "f"(s), "f"(q) : "memory");
}

__global__ __launch_bounds__(HTHR)
void hist_kernel(const float* __restrict__ preds,
                 const int*   __restrict__ times,
                 const int*   __restrict__ obsv,
                 int n) {
    const int n4 = n >> 2;
    const float4* p4 = (const float4*)preds;
    const int4*   t4 = (const int4*)times;
    const int4*   o4 = (const int4*)obsv;

    const int gtid    = blockIdx.x * HTHR + threadIdx.x;
    const int gstride = HBLK * HTHR;

    for (int i = gtid; i < n4; i += gstride) {
        float4 p = p4[i];
        int4   t = t4[i];
        int4   o = o4[i];
        acc_one(p.x, t.x, o.x);
        acc_one(p.y, t.y, o.y);
        acc_one(p.z, t.z, o.z);
        acc_one(p.w, t.w, o.w);
    }
    for (int i = (n4 << 2) + gtid; i < n; i += gstride)   // tail n%4
        acc_one(preds[i], times[i], obsv[i]);
}

// ---------------------------------------------------------------------------
// Kernel 2: single block — unpack and suffix-scan ONLY (no lgamma).
// Writes S,P,M,O,R to globals; resets g_acc2 for the next replay.
// ---------------------------------------------------------------------------
__global__ __launch_bounds__(FIN_THREADS, 1)
void scan_kernel() {
    __shared__ double sbuf[FIN_THREADS];
    const int tid = threadIdx.x;

    double S[8];
    double chunk = 0.0;
    #pragma unroll
    for (int k = 0; k < 8; k++) {
        int b = tid * 8 + k;
        float2 a = g_acc2[b];
        g_acc2[b] = make_float2(0.f, 0.f);        // reset for next replay
        double sp = (double)a.x;                  // S + obs_cnt*16384
        double pp = (double)a.y;                  // P + m*2048
        int m   = (int)floor(pp / (double)CNT_STEP + 0.5);
        int ocn = (int)floor(sp / (double)OBS_STEP);
        S[k] = sp - (double)ocn * (double)OBS_STEP;
        g_Sv[b] = (float)S[k];
        g_Pv[b] = (float)(pp - (double)m * (double)CNT_STEP);
        g_Mv[b] = m;
        g_Ov[b] = (ocn > 0) ? 1 : 0;
        chunk += S[k];
    }

    // inclusive suffix scan of per-thread chunk sums (Hillis–Steele)
    sbuf[tid] = chunk;
    __syncthreads();
    for (int off = 1; off < FIN_THREADS; off <<= 1) {
        double add = (tid + off < FIN_THREADS) ? sbuf[tid + off] : 0.0;
        __syncthreads();
        sbuf[tid] += add;
        __syncthreads();
    }
    double run = sbuf[tid] - chunk;               // suffix over later chunks

    #pragma unroll
    for (int k = 7; k >= 0; k--) {
        run += S[k];
        g_R[tid * 8 + k] = run;
    }
}

// ---------------------------------------------------------------------------
// Kernel 3: grid-wide Efron evaluation — one bucket per thread, lgammas
// spread over all SMs. Per-block double reduction + one atomicAdd.
//   efron_t = m*log(S/m) + lgamma(x+1) - lgamma(x+1-m),  x = R*m/S.
// ---------------------------------------------------------------------------
__global__ __launch_bounds__(256)
void efron_kernel() {
    __shared__ double sbuf[256];
    int b = blockIdx.x * 256 + threadIdx.x;

    double contrib = 0.0;
    int m = g_Mv[b];
    if (m > 0 && g_Ov[b]) {
        double md = (double)m;
        double a  = (double)g_Sv[b] / md;
        double x  = g_R[b] / a;                   // >= m
        contrib = (double)g_Pv[b]
                - (md * log(a) + lgamma(x + 1.0) - lgamma(x + 1.0 - md));
    }

    sbuf[threadIdx.x] = contrib;
    __syncthreads();
    for (int off = 128; off > 0; off >>= 1) {
        if (threadIdx.x < off) sbuf[threadIdx.x] += sbuf[threadIdx.x + off];
        __syncthreads();
    }
    if (threadIdx.x == 0) atomicAdd(&g_loss, sbuf[0]);
}

// ---------------------------------------------------------------------------
// Kernel 4: finalize — write output, reset loss accumulator.
// ---------------------------------------------------------------------------
__global__ void finalize_kernel(float* __restrict__ out) {
    out[0] = (float)(-g_loss);
    g_loss = 0.0;
}

// ---------------------------------------------------------------------------
extern "C" void kernel_launch(void* const* d_in, const int* in_sizes, int n_in,
                              void* d_out, int out_size) {
    const float* preds = (const float*)d_in[0];
    const int*   times = (const int*)d_in[1];
    const int*   obsv  = (const int*)d_in[2];
    int n = in_sizes[0];

    hist_kernel    <<<HBLK, HTHR>>>(preds, times, obsv, n);
    scan_kernel    <<<1, FIN_THREADS>>>();
    efron_kernel   <<<T_BUCKETS / 256, 256>>>();
    finalize_kernel<<<1, 1>>>((float*)d_out);
}

// round 9
// speedup vs baseline: 1.3156x; 1.3156x over previous
#include <cuda_runtime.h>
#include <math.h>

#define T_BUCKETS 8192
#define HBLK 1184
#define HTHR 256
#define FIN_THREADS 1024
#define EBLK (T_BUCKETS / 256)

// Per-bucket accumulator {S=sum exp, P=sum p, count, obs_count} (128 KB, L2).
// Zero at module load; efron_kernel resets it each launch after reading.
__device__ float4 g_acc[T_BUCKETS];
__device__ double g_R[T_BUCKETS];        // suffix sums of S
__device__ double g_loss;                // zero at load; last efron block resets
__device__ unsigned int g_ticket;        // efron completion counter

// ---------------------------------------------------------------------------
// Kernel 1: streaming histogram — ONE red.global.add.v4.f32 per element.
// EXACT R4 configuration (fastest measured: ~75us): precise expf, 1184x256.
// ---------------------------------------------------------------------------
__device__ __forceinline__ void red_v4(float4* addr, float e, float p, float o) {
    asm volatile("red.global.add.v4.f32 [%0], {%1, %2, %3, %4};"
                 :: "l"(addr), "f"(e), "f"(p), "f"(1.0f), "f"(o)
                 : "memory");
}

__global__ __launch_bounds__(HTHR)
void hist_kernel(const float* __restrict__ preds,
                 const int*   __restrict__ times,
                 const int*   __restrict__ obsv,
                 int n) {
    const int n4 = n >> 2;
    const float4* p4 = (const float4*)preds;
    const int4*   t4 = (const int4*)times;
    const int4*   o4 = (const int4*)obsv;

    const int gtid    = blockIdx.x * HTHR + threadIdx.x;
    const int gstride = HBLK * HTHR;

    for (int i = gtid; i < n4; i += gstride) {
        float4 p = p4[i];
        int4   t = t4[i];
        int4   o = o4[i];
        red_v4(&g_acc[t.x], expf(p.x), p.x, o.x ? 1.0f : 0.0f);
        red_v4(&g_acc[t.y], expf(p.y), p.y, o.y ? 1.0f : 0.0f);
        red_v4(&g_acc[t.z], expf(p.z), p.z, o.z ? 1.0f : 0.0f);
        red_v4(&g_acc[t.w], expf(p.w), p.w, o.w ? 1.0f : 0.0f);
    }
    for (int i = (n4 << 2) + gtid; i < n; i += gstride) {   // tail n%4
        float p = preds[i];
        red_v4(&g_acc[times[i]], expf(p), p, obsv[i] ? 1.0f : 0.0f);
    }
}

// ---------------------------------------------------------------------------
// Kernel 2: single block — double suffix-scan of S only (no lgamma).
// Leaves g_acc intact (efron reads + resets it).
// ---------------------------------------------------------------------------
__global__ __launch_bounds__(FIN_THREADS, 1)
void scan_kernel() {
    __shared__ double sbuf[FIN_THREADS];
    const int tid = threadIdx.x;

    double S[8];
    double chunk = 0.0;
    #pragma unroll
    for (int k = 0; k < 8; k++) {
        S[k] = (double)g_acc[tid * 8 + k].x;
        chunk += S[k];
    }

    sbuf[tid] = chunk;
    __syncthreads();
    for (int off = 1; off < FIN_THREADS; off <<= 1) {
        double add = (tid + off < FIN_THREADS) ? sbuf[tid + off] : 0.0;
        __syncthreads();
        sbuf[tid] += add;
        __syncthreads();
    }
    double run = sbuf[tid] - chunk;   // exclusive suffix over later chunks

    #pragma unroll
    for (int k = 7; k >= 0; k--) {
        run += S[k];
        g_R[tid * 8 + k] = run;
    }
}

// ---------------------------------------------------------------------------
// Kernel 3: grid-wide Efron closed form, one bucket/thread:
//   efron_t = m*log(S/m) + lgamma(x+1) - lgamma(x+1-m),  x = R*m/S >= m
//   contrib = obs_t ? (P_t - efron_t) : 0
// Block-reduce -> atomicAdd(g_loss). Each thread resets its own g_acc slot.
// The LAST block (ticket) writes out = -g_loss and resets g_loss/g_ticket.
// ---------------------------------------------------------------------------
__global__ __launch_bounds__(256)
void efron_kernel(float* __restrict__ out) {
    __shared__ double sbuf[256];
    int b = blockIdx.x * 256 + threadIdx.x;

    float4 a = g_acc[b];
    g_acc[b] = make_float4(0.f, 0.f, 0.f, 0.f);   // reset for next replay

    double contrib = 0.0;
    int m = (int)a.z;
    if (m > 0 && a.w > 0.0f) {
        double md = (double)m;
        double Sd = (double)a.x;
        double al = Sd / md;
        double x  = g_R[b] / al;                  // >= m
        contrib = (double)a.y
                - (md * log(al) + lgamma(x + 1.0) - lgamma(x + 1.0 - md));
    }

    sbuf[threadIdx.x] = contrib;
    __syncthreads();
    for (int off = 128; off > 0; off >>= 1) {
        if (threadIdx.x < off) sbuf[threadIdx.x] += sbuf[threadIdx.x + off];
        __syncthreads();
    }

    if (threadIdx.x == 0) {
        atomicAdd(&g_loss, sbuf[0]);
        __threadfence();
        unsigned int done = atomicAdd(&g_ticket, 1u);
        if (done == EBLK - 1) {                   // last block finalizes
            out[0] = (float)(-g_loss);
            g_loss = 0.0;
            g_ticket = 0u;
        }
    }
}

// ---------------------------------------------------------------------------
extern "C" void kernel_launch(void* const* d_in, const int* in_sizes, int n_in,
                              void* d_out, int out_size) {
    const float* preds = (const float*)d_in[0];
    const int*   times = (const int*)d_in[1];
    const int*   obsv  = (const int*)d_in[2];
    int n = in_sizes[0];

    hist_kernel <<<HBLK, HTHR>>>(preds, times, obsv, n);
    scan_kernel <<<1, FIN_THREADS>>>();
    efron_kernel<<<EBLK, 256>>>((float*)d_out);
}